// round 15
// baseline (speedup 1.0000x reference)
#include <cuda_runtime.h>
#include <cuda_bf16.h>
#include <math.h>

// Problem constants
#define SQ   1024
#define DIM  7168
#define NH   128
#define DNOPE 128
#define DROPE 64
#define DVAL 128
#define DQH  192         // DNOPE + DROPE
#define RQ   1536
#define RKV  512
#define HDQ  (NH*DQH)            // 24576
#define HKV  (NH*(DNOPE+DVAL))   // 32768
#define HDV  (NH*DVAL)           // 16384
#define EPS  1e-6f
#define NCAT 2176                // RQ + RKV + DROPE = 2112, padded to 17*128

// Scratch (device globals: allocation-free per harness rules; zero-init -> pads stay 0)
__device__ float g_hid  [SQ*DIM];
__device__ float g_wqkva[NCAT*DIM];
__device__ float g_qkva [SQ*NCAT];
__device__ float g_qan  [SQ*RQ];
__device__ float g_wqb  [HDQ*RQ];
__device__ float g_q    [SQ*HDQ];
__device__ float g_kvn  [SQ*RKV];
__device__ float g_wkvb [HKV*RKV];
__device__ float g_kv   [SQ*HKV];
__device__ float g_kpe  [SQ*DROPE];
__device__ float g_ao   [SQ*HDV];
__device__ float g_wo   [DIM*HDV];

// ---------------------------------------------------------------------------
// helpers
// ---------------------------------------------------------------------------
__device__ __forceinline__ unsigned f2tf(float f) {
  unsigned u;
  asm("cvt.rna.tf32.f32 %0, %1;" : "=r"(u) : "f"(f));
  return u;
}
__device__ __forceinline__ float rtf(float f) { return __uint_as_float(f2tf(f)); }

__device__ __forceinline__ unsigned smem_u32(const void* p){
  unsigned a;
  asm("{ .reg .u64 t; cvta.to.shared.u64 t, %1; cvt.u32.u64 %0, t; }" : "=r"(a) : "l"(p));
  return a;
}
__device__ __forceinline__ void cp16(unsigned dst, const float* src){
  asm volatile("cp.async.cg.shared.global [%0], [%1], 16;" :: "r"(dst), "l"(src));
}
__device__ __forceinline__ void cp_commit(){ asm volatile("cp.async.commit_group;" ::: "memory"); }
__device__ __forceinline__ void cp_wait2(){ asm volatile("cp.async.wait_group 2;" ::: "memory"); }

__device__ __forceinline__ void mma_tf32(float* d, const unsigned* a, const unsigned* b) {
  asm volatile(
    "mma.sync.aligned.m16n8k8.row.col.f32.tf32.tf32.f32 "
    "{%0,%1,%2,%3},{%4,%5,%6,%7},{%8,%9},{%0,%1,%2,%3};"
    : "+f"(d[0]), "+f"(d[1]), "+f"(d[2]), "+f"(d[3])
    : "r"(a[0]), "r"(a[1]), "r"(a[2]), "r"(a[3]), "r"(b[0]), "r"(b[1]));
}

__device__ __forceinline__ float4 rtf4(float4 v) {
  return make_float4(rtf(v.x), rtf(v.y), rtf(v.z), rtf(v.w));
}

// Fused tf32 pre-rounding of all six operands in ONE launch (so ncu's
// -s 5 -c 1 capture lands on a GEMM launch, and launch overhead shrinks).
__global__ void __launch_bounds__(256) roundall_kernel(
    const float4* s0, float4* d0, int n0,
    const float4* s1, float4* d1, int n1,
    const float4* s2, float4* d2, int n2,
    const float4* s3, float4* d3, int n3,
    const float4* s4, float4* d4, int n4,
    const float4* s5, float4* d5, int n5) {
  int i = blockIdx.x * 256 + threadIdx.x;
  if (i < n0) { d0[i] = rtf4(s0[i]); return; } i -= n0;
  if (i < n1) { d1[i] = rtf4(s1[i]); return; } i -= n1;
  if (i < n2) { d2[i] = rtf4(s2[i]); return; } i -= n2;
  if (i < n3) { d3[i] = rtf4(s3[i]); return; } i -= n3;
  if (i < n4) { d4[i] = rtf4(s4[i]); return; } i -= n4;
  if (i < n5) { d5[i] = rtf4(s5[i]); }
}

// ---------------------------------------------------------------------------
// TF32 tensor-core NT GEMM, cp.async 4-stage pipeline (R6 structure,
// register-lean rewrite: target <=128 regs at 2 CTAs/SM with NO spills).
// C[M,N] = A[M,K] * B[N,K]^T, row-major, operands PRE-ROUNDED to tf32 values.
// CTA tile 128x128x16, 256 threads, warp tile 64x32 (m16n8k8).
// Requires M%128==0, N%128==0, K%16==0, K>=64.
// smem: 4 stages x (A 8KB + B 8KB) = 64KB dynamic. XOR swizzle:
//   word(row,k) = row*16 + ((k>>2) ^ SWZ(row))*4 + (k&3),
//   SWZ(r) = ((r ^ (r>>2)) & 3);  note SWZ(r+8) == SWZ(r) ^ 2.
// ---------------------------------------------------------------------------
#define STAGES 4
#define AW 2048   // words per stage per operand (128 rows * 16 k)

__global__ void __launch_bounds__(256, 2) gemm_tf32_cp(
    const float* __restrict__ A, const float* __restrict__ B,
    float* __restrict__ C, int M, int N, int K) {
  extern __shared__ unsigned sm[];
  const int KT = K >> 4;
  const int bm = blockIdx.x * 128;
  const int bn = blockIdx.y * 128;
  const int tid  = threadIdx.x;
  const int lane = tid & 31;
  const int w    = tid >> 5;
  const int wm   = (w & 1) * 64;
  const int wn   = (w >> 1) * 32;
  const int g    = lane >> 2;
  const int tig  = lane & 3;

  // staging: thread -> 2 A chunks + 2 B chunks (16B each) per stage
  const int sr = tid >> 2;        // 0..63
  const int kc = tid & 3;         // chunk (4 k-values)
  const float* gA0 = A + (size_t)(bm + sr) * K + kc * 4;
  const float* gA1 = gA0 + (size_t)64 * K;
  const float* gB0 = B + (size_t)(bn + sr) * K + kc * 4;
  const float* gB1 = gB0 + (size_t)64 * K;
  const unsigned sb = smem_u32(sm);
  #define SWZ(r) (((r) ^ ((r) >> 2)) & 3)
  const unsigned dA0 = sb + 4u * ( sr      * 16 + ((kc ^ SWZ(sr))      << 2) );
  const unsigned dA1 = sb + 4u * ((sr + 64)* 16 + ((kc ^ SWZ(sr + 64)) << 2) );
  const unsigned dB0 = dA0 + 4u * STAGES * AW;
  const unsigned dB1 = dA1 + 4u * STAGES * AW;

  // fragment addressing (word offsets; per-chunk xor applied inline).
  // Row r0+8 = +128 words with swizzle ^2 (SWZ(r+8)==SWZ(r)^2) -> no arrays.
  int aw[4], asz[4], bw[4], bsz[4];
#pragma unroll
  for (int mt = 0; mt < 4; mt++) {
    const int r0 = wm + mt * 16 + g;
    aw[mt]  = r0 * 16 + tig;
    asz[mt] = SWZ(r0);
  }
#pragma unroll
  for (int nt = 0; nt < 4; nt++) {
    const int cn = wn + nt * 8 + g;
    bw[nt]  = cn * 16 + tig;
    bsz[nt] = SWZ(cn);
  }

  float acc[4][4][4];
#pragma unroll
  for (int mt = 0; mt < 4; mt++)
#pragma unroll
    for (int nt = 0; nt < 4; nt++)
#pragma unroll
      for (int i = 0; i < 4; i++) acc[mt][nt][i] = 0.f;

  auto issue = [&](int s) {
    if (s < KT) {
      const unsigned so = ((unsigned)(s & 3) * AW) << 2;
      const size_t go = (size_t)s * 16;
      cp16(dA0 + so, gA0 + go);
      cp16(dA1 + so, gA1 + go);
      cp16(dB0 + so, gB0 + go);
      cp16(dB1 + so, gB1 + go);
    }
    cp_commit();
  };
  issue(0); issue(1); issue(2);

  for (int kt = 0; kt < KT; ++kt) {
    cp_wait2();
    __syncthreads();
    issue(kt + 3);
    const unsigned aB = (unsigned)(kt & 3) * AW;
    const unsigned bB = STAGES * AW + (unsigned)(kt & 3) * AW;
#pragma unroll
    for (int ks = 0; ks < 2; ++ks) {
      const int c0 = ks << 1;
      unsigned bf[4][2];
#pragma unroll
      for (int nt = 0; nt < 4; nt++) {
        bf[nt][0] = sm[bB + bw[nt] + (((c0    ) ^ bsz[nt]) << 2)];
        bf[nt][1] = sm[bB + bw[nt] + (((c0 + 1) ^ bsz[nt]) << 2)];
      }
#pragma unroll
      for (int mt = 0; mt < 4; mt++) {
        unsigned af[4];
        const int x0 = (c0    ) ^ asz[mt];
        const int x1 = (c0 + 1) ^ asz[mt];
        af[0] = sm[aB + aw[mt]       + ( x0      << 2)];
        af[1] = sm[aB + aw[mt] + 128 + ((x0 ^ 2) << 2)];
        af[2] = sm[aB + aw[mt]       + ( x1      << 2)];
        af[3] = sm[aB + aw[mt] + 128 + ((x1 ^ 2) << 2)];
#pragma unroll
        for (int nt = 0; nt < 4; nt++)
          mma_tf32(acc[mt][nt], af, bf[nt]);
      }
    }
  }

  // epilogue
#pragma unroll
  for (int mt = 0; mt < 4; mt++) {
    const int row = bm + wm + mt * 16 + g;
#pragma unroll
    for (int nt = 0; nt < 4; nt++) {
      const int col = bn + wn + nt * 8 + 2 * tig;
      *(float2*)(C + (size_t)row * N + col)       = make_float2(acc[mt][nt][0], acc[mt][nt][1]);
      *(float2*)(C + (size_t)(row + 8) * N + col) = make_float2(acc[mt][nt][2], acc[mt][nt][3]);
    }
  }
}

// ---------------------------------------------------------------------------
// RMSNorm: out = x * rsqrt(mean(x^2)+eps) * w, rounded to tf32 for next GEMM.
// ---------------------------------------------------------------------------
__global__ void __launch_bounds__(256) rmsnorm_kernel(
    const float* __restrict__ in, const float* __restrict__ w,
    float* __restrict__ out, int n, int istride, int ostride) {
  const int row = blockIdx.x;
  const float* x = in + (size_t)row * istride;
  float s = 0.f;
  for (int i = threadIdx.x; i < n; i += 256) { float v = x[i]; s += v*v; }
  __shared__ float red[256];
  red[threadIdx.x] = s;
  __syncthreads();
  for (int off = 128; off > 0; off >>= 1) {
    if (threadIdx.x < off) red[threadIdx.x] += red[threadIdx.x + off];
    __syncthreads();
  }
  const float inv = rsqrtf(red[0] / (float)n + EPS);
  float* o = out + (size_t)row * ostride;
  for (int i = threadIdx.x; i < n; i += 256) o[i] = rtf(x[i] * inv * w[i]);
}

// ---------------------------------------------------------------------------
// RoPE on q_pe (in-place in g_q).
// ---------------------------------------------------------------------------
__global__ void rope_q_kernel(float* __restrict__ q,
                              const float* __restrict__ cosb,
                              const float* __restrict__ sinb) {
  int idx = blockIdx.x * blockDim.x + threadIdx.x;   // SQ*NH*32
  int d = idx & 31;
  int h = (idx >> 5) & (NH - 1);
  int s = idx >> 12;
  float* base = q + (size_t)s * HDQ + h * DQH + DNOPE;
  float x1 = base[d], x2 = base[d + 32];
  float c1 = cosb[s*DROPE + d],      s1 = sinb[s*DROPE + d];
  float c2 = cosb[s*DROPE + d + 32], s2 = sinb[s*DROPE + d + 32];
  base[d]      = x1*c1 - x2*s1;
  base[d + 32] = x2*c2 + x1*s2;
}

// RoPE on k_pe (from qkva cols [2048, 2112)) -> g_kpe[S, 64]
__global__ void rope_k_kernel(const float* __restrict__ qkva,
                              const float* __restrict__ cosb,
                              const float* __restrict__ sinb,
                              float* __restrict__ kpe) {
  int idx = blockIdx.x * blockDim.x + threadIdx.x;  // SQ*32
  int d = idx & 31;
  int s = idx >> 5;
  float x1 = qkva[(size_t)s*NCAT + (RQ+RKV) + d];
  float x2 = qkva[(size_t)s*NCAT + (RQ+RKV) + 32 + d];
  float c1 = cosb[s*DROPE + d],      s1 = sinb[s*DROPE + d];
  float c2 = cosb[s*DROPE + d + 32], s2 = sinb[s*DROPE + d + 32];
  kpe[s*DROPE + d]      = x1*c1 - x2*s1;
  kpe[s*DROPE + 32 + d] = x2*c2 + x1*s2;
}

// ---------------------------------------------------------------------------
// Flash attention (causal), register-blocked (R11-proven). One block per
// (head, 64-row q tile), 256 threads as 16x16: thread (ty,tx) owns a 4x4
// score tile and a 4x8 output tile. Output rounded to tf32 (feeds wo GEMM).
// Ps has odd word stride (65) -> scalar P stores (float4 would misalign).
// ---------------------------------------------------------------------------
#define QK_STR 196
#define PS_STR 65
#define FLASH_SMEM ((2*64*QK_STR + 64*128 + 64*PS_STR) * 4)

__global__ void __launch_bounds__(256) flash_kernel(
    const float* __restrict__ q, const float* __restrict__ kv,
    const float* __restrict__ kpe, float* __restrict__ ao) {
  extern __shared__ float smf[];
  float* Qs = smf;                     // 64 x QK_STR
  float* Ks = Qs + 64*QK_STR;          // 64 x QK_STR
  float* Vs = Ks + 64*QK_STR;          // 64 x 128
  float* Ps = Vs + 64*128;             // 64 x PS_STR

  const int h  = blockIdx.x;
  const int q0 = blockIdx.y * 64;
  const int tid = threadIdx.x;
  const int tx = tid & 15;
  const int ty = tid >> 4;
  const int r0 = ty * 4;               // q-row group
  const int c0 = tx * 4;               // score-col group
  const int oc = tx * 8;               // out-col group

  for (int idx = tid; idx < 64*DQH; idx += 256) {
    int row = idx / DQH, d = idx % DQH;
    Qs[row*QK_STR + d] = q[(size_t)(q0+row)*HDQ + h*DQH + d];
  }

  float m[4], l[4], o[4][8];
#pragma unroll
  for (int r = 0; r < 4; r++) {
    m[r] = -INFINITY; l[r] = 0.f;
#pragma unroll
    for (int c = 0; c < 8; c++) o[r][c] = 0.f;
  }
  const float scale = rsqrtf((float)DQH);

  const int nkt = blockIdx.y + 1;
  for (int kt = 0; kt < nkt; kt++) {
    const int k0 = kt * 64;
    __syncthreads();
    for (int idx = tid; idx < 64*DQH; idx += 256) {
      int row = idx / DQH, d = idx % DQH;
      Ks[row*QK_STR + d] = (d < DNOPE)
          ? kv[(size_t)(k0+row)*HKV + h*(DNOPE+DVAL) + d]
          : kpe[(k0+row)*DROPE + (d - DNOPE)];
    }
    for (int idx = tid; idx < 64*128; idx += 256) {
      int row = idx >> 7, d = idx & 127;
      Vs[idx] = kv[(size_t)(k0+row)*HKV + h*(DNOPE+DVAL) + DNOPE + d];
    }
    __syncthreads();

    // scores: 4x4 microtile, float4 over d
    float sc[4][4];
#pragma unroll
    for (int r = 0; r < 4; r++)
#pragma unroll
      for (int c = 0; c < 4; c++) sc[r][c] = 0.f;

    for (int d0 = 0; d0 < DQH; d0 += 4) {
      float4 qv[4], kv4[4];
#pragma unroll
      for (int r = 0; r < 4; r++) qv[r]  = *(const float4*)&Qs[(r0+r)*QK_STR + d0];
#pragma unroll
      for (int c = 0; c < 4; c++) kv4[c] = *(const float4*)&Ks[(c0+c)*QK_STR + d0];
#pragma unroll
      for (int r = 0; r < 4; r++)
#pragma unroll
        for (int c = 0; c < 4; c++) {
          sc[r][c] += qv[r].x*kv4[c].x + qv[r].y*kv4[c].y
                    + qv[r].z*kv4[c].z + qv[r].w*kv4[c].w;
        }
    }

    if (kt == nkt - 1) {     // only the diagonal tile needs the causal mask
#pragma unroll
      for (int r = 0; r < 4; r++)
#pragma unroll
        for (int c = 0; c < 4; c++)
          sc[r][c] = (k0 + c0 + c <= q0 + r0 + r) ? sc[r][c]*scale : -INFINITY;
    } else {
#pragma unroll
      for (int r = 0; r < 4; r++)
#pragma unroll
        for (int c = 0; c < 4; c++) sc[r][c] *= scale;
    }

    // online softmax: reduce over tx (16 lanes)
    float alpha[4];
#pragma unroll
    for (int r = 0; r < 4; r++) {
      float mloc = fmaxf(fmaxf(sc[r][0], sc[r][1]), fmaxf(sc[r][2], sc[r][3]));
      mloc = fmaxf(mloc, __shfl_xor_sync(0xffffffffu, mloc, 1));
      mloc = fmaxf(mloc, __shfl_xor_sync(0xffffffffu, mloc, 2));
      mloc = fmaxf(mloc, __shfl_xor_sync(0xffffffffu, mloc, 4));
      mloc = fmaxf(mloc, __shfl_xor_sync(0xffffffffu, mloc, 8));
      float mnew = fmaxf(m[r], mloc);
      alpha[r] = expf(m[r] - mnew);
      float lloc = 0.f;
#pragma unroll
      for (int c = 0; c < 4; c++) {
        float p = expf(sc[r][c] - mnew);
        sc[r][c] = p;
        lloc += p;
      }
      lloc += __shfl_xor_sync(0xffffffffu, lloc, 1);
      lloc += __shfl_xor_sync(0xffffffffu, lloc, 2);
      lloc += __shfl_xor_sync(0xffffffffu, lloc, 4);
      lloc += __shfl_xor_sync(0xffffffffu, lloc, 8);
      l[r] = l[r] * alpha[r] + lloc;
      m[r] = mnew;
#pragma unroll
      for (int c = 0; c < 8; c++) o[r][c] *= alpha[r];
      // scalar stores: Ps row stride 65 words is not 16B-aligned
      Ps[(r0+r)*PS_STR + c0    ] = sc[r][0];
      Ps[(r0+r)*PS_STR + c0 + 1] = sc[r][1];
      Ps[(r0+r)*PS_STR + c0 + 2] = sc[r][2];
      Ps[(r0+r)*PS_STR + c0 + 3] = sc[r][3];
    }
    __syncthreads();   // Ps visible to all before PV

    // PV: thread accumulates rows r0..r0+3 x cols oc..oc+7
    for (int j = 0; j < 64; j++) {
      float4 v0 = *(const float4*)&Vs[j*128 + oc];
      float4 v1 = *(const float4*)&Vs[j*128 + oc + 4];
      float pv[4];
#pragma unroll
      for (int r = 0; r < 4; r++) pv[r] = Ps[(r0+r)*PS_STR + j];
#pragma unroll
      for (int r = 0; r < 4; r++) {
        o[r][0] += pv[r]*v0.x; o[r][1] += pv[r]*v0.y;
        o[r][2] += pv[r]*v0.z; o[r][3] += pv[r]*v0.w;
        o[r][4] += pv[r]*v1.x; o[r][5] += pv[r]*v1.y;
        o[r][6] += pv[r]*v1.z; o[r][7] += pv[r]*v1.w;
      }
    }
  }

#pragma unroll
  for (int r = 0; r < 4; r++) {
    const float invl = 1.f / l[r];
    float* op = ao + (size_t)(q0 + r0 + r)*HDV + h*DVAL + oc;
#pragma unroll
    for (int c = 0; c < 8; c++) op[c] = rtf(o[r][c] * invl);
  }
}

// ---------------------------------------------------------------------------
extern "C" void kernel_launch(void* const* d_in, const int* in_sizes, int n_in,
                              void* d_out, int out_size) {
  const float* hidden  = (const float*)d_in[0];
  const float* cosb    = (const float*)d_in[1];
  const float* sinb    = (const float*)d_in[2];
  const float* wq_a    = (const float*)d_in[3];
  const float* q_ln_w  = (const float*)d_in[4];
  const float* wq_b    = (const float*)d_in[5];
  const float* wkv_a   = (const float*)d_in[6];
  const float* kv_ln_w = (const float*)d_in[7];
  const float* wkv_b   = (const float*)d_in[8];
  const float* wo      = (const float*)d_in[9];
  float* out = (float*)d_out;

  float *hid, *wqkva, *qkva, *qan, *wqb, *q, *kvn, *wkvb, *kv, *kpe, *ao, *woR;
  cudaGetSymbolAddress((void**)&hid,   g_hid);
  cudaGetSymbolAddress((void**)&wqkva, g_wqkva);
  cudaGetSymbolAddress((void**)&qkva,  g_qkva);
  cudaGetSymbolAddress((void**)&qan,   g_qan);
  cudaGetSymbolAddress((void**)&wqb,   g_wqb);
  cudaGetSymbolAddress((void**)&q,     g_q);
  cudaGetSymbolAddress((void**)&kvn,   g_kvn);
  cudaGetSymbolAddress((void**)&wkvb,  g_wkvb);
  cudaGetSymbolAddress((void**)&kv,    g_kv);
  cudaGetSymbolAddress((void**)&kpe,   g_kpe);
  cudaGetSymbolAddress((void**)&ao,    g_ao);
  cudaGetSymbolAddress((void**)&woR,   g_wo);

  const int GSM = STAGES * 2 * AW * 4;   // 64KB
  cudaFuncSetAttribute(gemm_tf32_cp, cudaFuncAttributeMaxDynamicSharedMemorySize, GSM);
  cudaFuncSetAttribute(flash_kernel, cudaFuncAttributeMaxDynamicSharedMemorySize, FLASH_SMEM);

  // fused tf32 pre-rounding of all operands (ONE launch)
  const int n0 = SQ*DIM/4;
  const int n1 = RQ*DIM/4;
  const int n2 = (RKV+DROPE)*DIM/4;
  const int n3 = HDQ*RQ/4;
  const int n4 = HKV*RKV/4;
  const int n5 = DIM*HDV/4;
  const int ntot = n0+n1+n2+n3+n4+n5;
  roundall_kernel<<<(ntot + 255)/256, 256>>>(
      (const float4*)hidden, (float4*)hid,   n0,
      (const float4*)wq_a,   (float4*)wqkva, n1,
      (const float4*)wkv_a,  (float4*)(wqkva + (size_t)RQ*DIM), n2,
      (const float4*)wq_b,   (float4*)wqb,   n3,
      (const float4*)wkv_b,  (float4*)wkvb,  n4,
      (const float4*)wo,     (float4*)woR,   n5);

  // fused q_a + kv_a projection: qkva[1024, 2176]
  gemm_tf32_cp<<<dim3(SQ/128, NCAT/128), 256, GSM>>>(hid, wqkva, qkva, SQ, NCAT, DIM);

  // q path
  rmsnorm_kernel<<<SQ, 256>>>(qkva, q_ln_w, qan, RQ, NCAT, RQ);
  gemm_tf32_cp<<<dim3(SQ/128, HDQ/128), 256, GSM>>>(qan, wqb, q, SQ, HDQ, RQ);

  // kv path
  rmsnorm_kernel<<<SQ, 256>>>(qkva + RQ, kv_ln_w, kvn, RKV, NCAT, RKV);
  gemm_tf32_cp<<<dim3(SQ/128, HKV/128), 256, GSM>>>(kvn, wkvb, kv, SQ, HKV, RKV);

  // RoPE
  rope_q_kernel<<<(SQ*NH*32)/256, 256>>>(q, cosb, sinb);
  rope_k_kernel<<<(SQ*32)/256, 256>>>(qkva, cosb, sinb, kpe);

  // causal flash attention (rounds its output)
  flash_kernel<<<dim3(NH, SQ/64), 256, FLASH_SMEM>>>(q, kv, kpe, ao);

  // output projection
  gemm_tf32_cp<<<dim3(SQ/128, DIM/128), 256, GSM>>>(ao, woR, out, SQ, DIM, HDV);
}

// round 16
// speedup vs baseline: 1.4557x; 1.4557x over previous
#include <cuda_runtime.h>
#include <cuda_bf16.h>
#include <math.h>

// Problem constants
#define SQ   1024
#define DIM  7168
#define NH   128
#define DNOPE 128
#define DROPE 64
#define DVAL 128
#define DQH  192         // DNOPE + DROPE
#define RQ   1536
#define RKV  512
#define HDQ  (NH*DQH)            // 24576
#define HKV  (NH*(DNOPE+DVAL))   // 32768
#define HDV  (NH*DVAL)           // 16384
#define EPS  1e-6f
#define NCAT 2176                // RQ + RKV + DROPE = 2112, padded to 17*128

// Scratch (device globals: allocation-free per harness rules; zero-init -> pads stay 0)
__device__ float g_hid  [SQ*DIM];
__device__ float g_wqkva[NCAT*DIM];
__device__ float g_qkva [SQ*NCAT];
__device__ float g_qan  [SQ*RQ];
__device__ float g_wqb  [HDQ*RQ];
__device__ float g_q    [SQ*HDQ];
__device__ float g_kvn  [SQ*RKV];
__device__ float g_wkvb [HKV*RKV];
__device__ float g_kv   [SQ*HKV];
__device__ float g_kpe  [SQ*DROPE];
__device__ float g_ao   [SQ*HDV];
__device__ float g_wo   [DIM*HDV];

// ---------------------------------------------------------------------------
// helpers
// ---------------------------------------------------------------------------
__device__ __forceinline__ unsigned f2tf(float f) {
  unsigned u;
  asm("cvt.rna.tf32.f32 %0, %1;" : "=r"(u) : "f"(f));
  return u;
}
__device__ __forceinline__ float rtf(float f) { return __uint_as_float(f2tf(f)); }

__device__ __forceinline__ unsigned smem_u32(const void* p){
  unsigned a;
  asm("{ .reg .u64 t; cvta.to.shared.u64 t, %1; cvt.u32.u64 %0, t; }" : "=r"(a) : "l"(p));
  return a;
}
__device__ __forceinline__ void cp16(unsigned dst, const float* src){
  asm volatile("cp.async.cg.shared.global [%0], [%1], 16;" :: "r"(dst), "l"(src));
}
__device__ __forceinline__ void cp_commit(){ asm volatile("cp.async.commit_group;" ::: "memory"); }
__device__ __forceinline__ void cp_wait2(){ asm volatile("cp.async.wait_group 2;" ::: "memory"); }

__device__ __forceinline__ void mma_tf32(float* d, const unsigned* a, const unsigned* b) {
  asm volatile(
    "mma.sync.aligned.m16n8k8.row.col.f32.tf32.tf32.f32 "
    "{%0,%1,%2,%3},{%4,%5,%6,%7},{%8,%9},{%0,%1,%2,%3};"
    : "+f"(d[0]), "+f"(d[1]), "+f"(d[2]), "+f"(d[3])
    : "r"(a[0]), "r"(a[1]), "r"(a[2]), "r"(a[3]), "r"(b[0]), "r"(b[1]));
}

__device__ __forceinline__ float4 rtf4(float4 v) {
  return make_float4(rtf(v.x), rtf(v.y), rtf(v.z), rtf(v.w));
}

// Fused tf32 pre-rounding of all six operands in ONE launch.
__global__ void __launch_bounds__(256) roundall_kernel(
    const float4* s0, float4* d0, int n0,
    const float4* s1, float4* d1, int n1,
    const float4* s2, float4* d2, int n2,
    const float4* s3, float4* d3, int n3,
    const float4* s4, float4* d4, int n4,
    const float4* s5, float4* d5, int n5) {
  int i = blockIdx.x * 256 + threadIdx.x;
  if (i < n0) { d0[i] = rtf4(s0[i]); return; } i -= n0;
  if (i < n1) { d1[i] = rtf4(s1[i]); return; } i -= n1;
  if (i < n2) { d2[i] = rtf4(s2[i]); return; } i -= n2;
  if (i < n3) { d3[i] = rtf4(s3[i]); return; } i -= n3;
  if (i < n4) { d4[i] = rtf4(s4[i]); return; } i -= n4;
  if (i < n5) { d5[i] = rtf4(s5[i]); }
}

// ---------------------------------------------------------------------------
// TF32 tensor-core NT GEMM, cp.async 6-stage ring, TWO k-stages per sync.
// C[M,N] = A[M,K] * B[N,K]^T, row-major, operands PRE-ROUNDED to tf32 values.
// CTA tile 128x128x16 per stage, 256 threads, warp tile 64x32 (m16n8k8).
// Inner loop = R11's proven grouped-load ordering (af[4][4], bf[4][2], 16 mma).
// Requires M%128==0, N%128==0, K%32==0 (KT even), K>=96.
// smem: 6 stages x (A 8KB + B 8KB) = 96KB dynamic; 2 CTAs/SM (192KB).
// Hazard schedule per iter kt (even): wait_group2 completes stages kt,kt+1;
// fills slots (kt+4)%6,(kt+5)%6 (computed 2 iters ago, sync since); computes
// slots kt%6,(kt+1)%6.
// ---------------------------------------------------------------------------
#define STAGES 6
#define AW 2048   // words per stage per operand (128 rows * 16 k)

__global__ void __launch_bounds__(256, 2) gemm_tf32_cp(
    const float* __restrict__ A, const float* __restrict__ B,
    float* __restrict__ C, int M, int N, int K) {
  extern __shared__ unsigned sm[];
  const int KT = K >> 4;
  const int bm = blockIdx.x * 128;
  const int bn = blockIdx.y * 128;
  const int tid  = threadIdx.x;
  const int lane = tid & 31;
  const int w    = tid >> 5;
  const int wm   = (w & 1) * 64;
  const int wn   = (w >> 1) * 32;
  const int g    = lane >> 2;
  const int tig  = lane & 3;

  // staging: thread -> 2 A chunks + 2 B chunks (16B each) per stage
  const int sr = tid >> 2;        // 0..63
  const int kc = tid & 3;         // chunk (4 k-values)
  const float* gA0 = A + (size_t)(bm + sr) * K + kc * 4;
  const float* gA1 = gA0 + (size_t)64 * K;
  const float* gB0 = B + (size_t)(bn + sr) * K + kc * 4;
  const float* gB1 = gB0 + (size_t)64 * K;
  const unsigned sb = smem_u32(sm);
  #define SWZ(r) (((r) ^ ((r) >> 2)) & 3)
  const unsigned dA0 = sb + 4u * ( sr      * 16 + ((kc ^ SWZ(sr))      << 2) );
  const unsigned dA1 = sb + 4u * ((sr + 64)* 16 + ((kc ^ SWZ(sr + 64)) << 2) );
  const unsigned dB0 = dA0 + 4u * STAGES * AW;
  const unsigned dB1 = dA1 + 4u * STAGES * AW;

  // fragment address precompute (word offsets; chunk xor applied inline)
  int aoff0[4], aoff1[4], asz0[4], asz1[4], boff[4], bsz[4];
#pragma unroll
  for (int mt = 0; mt < 4; mt++) {
    int r0 = wm + mt * 16 + g, r1 = r0 + 8;
    aoff0[mt] = r0 * 16 + tig; asz0[mt] = SWZ(r0);
    aoff1[mt] = r1 * 16 + tig; asz1[mt] = SWZ(r1);
  }
#pragma unroll
  for (int nt = 0; nt < 4; nt++) {
    int cn = wn + nt * 8 + g;
    boff[nt] = cn * 16 + tig; bsz[nt] = SWZ(cn);
  }

  float acc[4][4][4];
#pragma unroll
  for (int mt = 0; mt < 4; mt++)
#pragma unroll
    for (int nt = 0; nt < 4; nt++)
#pragma unroll
      for (int i = 0; i < 4; i++) acc[mt][nt][i] = 0.f;

  auto issue = [&](int s, int slot) {
    if (s < KT) {
      const unsigned so = ((unsigned)slot * AW) << 2;
      const size_t go = (size_t)s * 16;
      cp16(dA0 + so, gA0 + go);
      cp16(dA1 + so, gA1 + go);
      cp16(dB0 + so, gB0 + go);
      cp16(dB1 + so, gB1 + go);
    }
    cp_commit();
  };

  auto compute = [&](int slot) {
    const unsigned aB = (unsigned)slot * AW;
    const unsigned bB = STAGES * AW + (unsigned)slot * AW;
#pragma unroll
    for (int ks = 0; ks < 2; ++ks) {
      const int kc0 = ks << 1;
      unsigned af[4][4], bf[4][2];
#pragma unroll
      for (int mt = 0; mt < 4; mt++) {
        af[mt][0] = sm[aB + aoff0[mt] + (((kc0    ) ^ asz0[mt]) << 2)];
        af[mt][1] = sm[aB + aoff1[mt] + (((kc0    ) ^ asz1[mt]) << 2)];
        af[mt][2] = sm[aB + aoff0[mt] + (((kc0 + 1) ^ asz0[mt]) << 2)];
        af[mt][3] = sm[aB + aoff1[mt] + (((kc0 + 1) ^ asz1[mt]) << 2)];
      }
#pragma unroll
      for (int nt = 0; nt < 4; nt++) {
        bf[nt][0] = sm[bB + boff[nt] + (((kc0    ) ^ bsz[nt]) << 2)];
        bf[nt][1] = sm[bB + boff[nt] + (((kc0 + 1) ^ bsz[nt]) << 2)];
      }
#pragma unroll
      for (int mt = 0; mt < 4; mt++)
#pragma unroll
        for (int nt = 0; nt < 4; nt++)
          mma_tf32(acc[mt][nt], af[mt], bf[nt]);
    }
  };

  // prologue: 4 stages in flight
  issue(0, 0); issue(1, 1); issue(2, 2); issue(3, 3);

  int cs = 0, fs = 4;
  for (int kt = 0; kt < KT; kt += 2) {
    cp_wait2();            // stages kt, kt+1 complete
    __syncthreads();
    issue(kt + 4, fs); fs = (fs + 1 == STAGES) ? 0 : fs + 1;
    issue(kt + 5, fs); fs = (fs + 1 == STAGES) ? 0 : fs + 1;
    compute(cs); cs = (cs + 1 == STAGES) ? 0 : cs + 1;
    compute(cs); cs = (cs + 1 == STAGES) ? 0 : cs + 1;
  }

  // epilogue
#pragma unroll
  for (int mt = 0; mt < 4; mt++) {
    const int row = bm + wm + mt * 16 + g;
#pragma unroll
    for (int nt = 0; nt < 4; nt++) {
      const int col = bn + wn + nt * 8 + 2 * tig;
      *(float2*)(C + (size_t)row * N + col)       = make_float2(acc[mt][nt][0], acc[mt][nt][1]);
      *(float2*)(C + (size_t)(row + 8) * N + col) = make_float2(acc[mt][nt][2], acc[mt][nt][3]);
    }
  }
}

// ---------------------------------------------------------------------------
// RMSNorm: out = x * rsqrt(mean(x^2)+eps) * w, rounded to tf32 for next GEMM.
// ---------------------------------------------------------------------------
__global__ void __launch_bounds__(256) rmsnorm_kernel(
    const float* __restrict__ in, const float* __restrict__ w,
    float* __restrict__ out, int n, int istride, int ostride) {
  const int row = blockIdx.x;
  const float* x = in + (size_t)row * istride;
  float s = 0.f;
  for (int i = threadIdx.x; i < n; i += 256) { float v = x[i]; s += v*v; }
  __shared__ float red[256];
  red[threadIdx.x] = s;
  __syncthreads();
  for (int off = 128; off > 0; off >>= 1) {
    if (threadIdx.x < off) red[threadIdx.x] += red[threadIdx.x + off];
    __syncthreads();
  }
  const float inv = rsqrtf(red[0] / (float)n + EPS);
  float* o = out + (size_t)row * ostride;
  for (int i = threadIdx.x; i < n; i += 256) o[i] = rtf(x[i] * inv * w[i]);
}

// ---------------------------------------------------------------------------
// RoPE on q_pe (in-place in g_q).
// ---------------------------------------------------------------------------
__global__ void rope_q_kernel(float* __restrict__ q,
                              const float* __restrict__ cosb,
                              const float* __restrict__ sinb) {
  int idx = blockIdx.x * blockDim.x + threadIdx.x;   // SQ*NH*32
  int d = idx & 31;
  int h = (idx >> 5) & (NH - 1);
  int s = idx >> 12;
  float* base = q + (size_t)s * HDQ + h * DQH + DNOPE;
  float x1 = base[d], x2 = base[d + 32];
  float c1 = cosb[s*DROPE + d],      s1 = sinb[s*DROPE + d];
  float c2 = cosb[s*DROPE + d + 32], s2 = sinb[s*DROPE + d + 32];
  base[d]      = x1*c1 - x2*s1;
  base[d + 32] = x2*c2 + x1*s2;
}

// RoPE on k_pe (from qkva cols [2048, 2112)) -> g_kpe[S, 64]
__global__ void rope_k_kernel(const float* __restrict__ qkva,
                              const float* __restrict__ cosb,
                              const float* __restrict__ sinb,
                              float* __restrict__ kpe) {
  int idx = blockIdx.x * blockDim.x + threadIdx.x;  // SQ*32
  int d = idx & 31;
  int s = idx >> 5;
  float x1 = qkva[(size_t)s*NCAT + (RQ+RKV) + d];
  float x2 = qkva[(size_t)s*NCAT + (RQ+RKV) + 32 + d];
  float c1 = cosb[s*DROPE + d],      s1 = sinb[s*DROPE + d];
  float c2 = cosb[s*DROPE + d + 32], s2 = sinb[s*DROPE + d + 32];
  kpe[s*DROPE + d]      = x1*c1 - x2*s1;
  kpe[s*DROPE + 32 + d] = x2*c2 + x1*s2;
}

// ---------------------------------------------------------------------------
// Flash attention (causal), register-blocked (R11-proven). One block per
// (head, 64-row q tile), 256 threads as 16x16: thread (ty,tx) owns a 4x4
// score tile and a 4x8 output tile. Output rounded to tf32 (feeds wo GEMM).
// Ps has odd word stride (65) -> scalar P stores (float4 would misalign).
// ---------------------------------------------------------------------------
#define QK_STR 196
#define PS_STR 65
#define FLASH_SMEM ((2*64*QK_STR + 64*128 + 64*PS_STR) * 4)

__global__ void __launch_bounds__(256) flash_kernel(
    const float* __restrict__ q, const float* __restrict__ kv,
    const float* __restrict__ kpe, float* __restrict__ ao) {
  extern __shared__ float smf[];
  float* Qs = smf;                     // 64 x QK_STR
  float* Ks = Qs + 64*QK_STR;          // 64 x QK_STR
  float* Vs = Ks + 64*QK_STR;          // 64 x 128
  float* Ps = Vs + 64*128;             // 64 x PS_STR

  const int h  = blockIdx.x;
  const int q0 = blockIdx.y * 64;
  const int tid = threadIdx.x;
  const int tx = tid & 15;
  const int ty = tid >> 4;
  const int r0 = ty * 4;               // q-row group
  const int c0 = tx * 4;               // score-col group
  const int oc = tx * 8;               // out-col group

  for (int idx = tid; idx < 64*DQH; idx += 256) {
    int row = idx / DQH, d = idx % DQH;
    Qs[row*QK_STR + d] = q[(size_t)(q0+row)*HDQ + h*DQH + d];
  }

  float m[4], l[4], o[4][8];
#pragma unroll
  for (int r = 0; r < 4; r++) {
    m[r] = -INFINITY; l[r] = 0.f;
#pragma unroll
    for (int c = 0; c < 8; c++) o[r][c] = 0.f;
  }
  const float scale = rsqrtf((float)DQH);

  const int nkt = blockIdx.y + 1;
  for (int kt = 0; kt < nkt; kt++) {
    const int k0 = kt * 64;
    __syncthreads();
    for (int idx = tid; idx < 64*DQH; idx += 256) {
      int row = idx / DQH, d = idx % DQH;
      Ks[row*QK_STR + d] = (d < DNOPE)
          ? kv[(size_t)(k0+row)*HKV + h*(DNOPE+DVAL) + d]
          : kpe[(k0+row)*DROPE + (d - DNOPE)];
    }
    for (int idx = tid; idx < 64*128; idx += 256) {
      int row = idx >> 7, d = idx & 127;
      Vs[idx] = kv[(size_t)(k0+row)*HKV + h*(DNOPE+DVAL) + DNOPE + d];
    }
    __syncthreads();

    // scores: 4x4 microtile, float4 over d
    float sc[4][4];
#pragma unroll
    for (int r = 0; r < 4; r++)
#pragma unroll
      for (int c = 0; c < 4; c++) sc[r][c] = 0.f;

    for (int d0 = 0; d0 < DQH; d0 += 4) {
      float4 qv[4], kv4[4];
#pragma unroll
      for (int r = 0; r < 4; r++) qv[r]  = *(const float4*)&Qs[(r0+r)*QK_STR + d0];
#pragma unroll
      for (int c = 0; c < 4; c++) kv4[c] = *(const float4*)&Ks[(c0+c)*QK_STR + d0];
#pragma unroll
      for (int r = 0; r < 4; r++)
#pragma unroll
        for (int c = 0; c < 4; c++) {
          sc[r][c] += qv[r].x*kv4[c].x + qv[r].y*kv4[c].y
                    + qv[r].z*kv4[c].z + qv[r].w*kv4[c].w;
        }
    }

    if (kt == nkt - 1) {     // only the diagonal tile needs the causal mask
#pragma unroll
      for (int r = 0; r < 4; r++)
#pragma unroll
        for (int c = 0; c < 4; c++)
          sc[r][c] = (k0 + c0 + c <= q0 + r0 + r) ? sc[r][c]*scale : -INFINITY;
    } else {
#pragma unroll
      for (int r = 0; r < 4; r++)
#pragma unroll
        for (int c = 0; c < 4; c++) sc[r][c] *= scale;
    }

    // online softmax: reduce over tx (16 lanes)
    float alpha[4];
#pragma unroll
    for (int r = 0; r < 4; r++) {
      float mloc = fmaxf(fmaxf(sc[r][0], sc[r][1]), fmaxf(sc[r][2], sc[r][3]));
      mloc = fmaxf(mloc, __shfl_xor_sync(0xffffffffu, mloc, 1));
      mloc = fmaxf(mloc, __shfl_xor_sync(0xffffffffu, mloc, 2));
      mloc = fmaxf(mloc, __shfl_xor_sync(0xffffffffu, mloc, 4));
      mloc = fmaxf(mloc, __shfl_xor_sync(0xffffffffu, mloc, 8));
      float mnew = fmaxf(m[r], mloc);
      alpha[r] = expf(m[r] - mnew);
      float lloc = 0.f;
#pragma unroll
      for (int c = 0; c < 4; c++) {
        float p = expf(sc[r][c] - mnew);
        sc[r][c] = p;
        lloc += p;
      }
      lloc += __shfl_xor_sync(0xffffffffu, lloc, 1);
      lloc += __shfl_xor_sync(0xffffffffu, lloc, 2);
      lloc += __shfl_xor_sync(0xffffffffu, lloc, 4);
      lloc += __shfl_xor_sync(0xffffffffu, lloc, 8);
      l[r] = l[r] * alpha[r] + lloc;
      m[r] = mnew;
#pragma unroll
      for (int c = 0; c < 8; c++) o[r][c] *= alpha[r];
      // scalar stores: Ps row stride 65 words is not 16B-aligned
      Ps[(r0+r)*PS_STR + c0    ] = sc[r][0];
      Ps[(r0+r)*PS_STR + c0 + 1] = sc[r][1];
      Ps[(r0+r)*PS_STR + c0 + 2] = sc[r][2];
      Ps[(r0+r)*PS_STR + c0 + 3] = sc[r][3];
    }
    __syncthreads();   // Ps visible to all before PV

    // PV: thread accumulates rows r0..r0+3 x cols oc..oc+7
    for (int j = 0; j < 64; j++) {
      float4 v0 = *(const float4*)&Vs[j*128 + oc];
      float4 v1 = *(const float4*)&Vs[j*128 + oc + 4];
      float pv[4];
#pragma unroll
      for (int r = 0; r < 4; r++) pv[r] = Ps[(r0+r)*PS_STR + j];
#pragma unroll
      for (int r = 0; r < 4; r++) {
        o[r][0] += pv[r]*v0.x; o[r][1] += pv[r]*v0.y;
        o[r][2] += pv[r]*v0.z; o[r][3] += pv[r]*v0.w;
        o[r][4] += pv[r]*v1.x; o[r][5] += pv[r]*v1.y;
        o[r][6] += pv[r]*v1.z; o[r][7] += pv[r]*v1.w;
      }
    }
  }

#pragma unroll
  for (int r = 0; r < 4; r++) {
    const float invl = 1.f / l[r];
    float* op = ao + (size_t)(q0 + r0 + r)*HDV + h*DVAL + oc;
#pragma unroll
    for (int c = 0; c < 8; c++) op[c] = rtf(o[r][c] * invl);
  }
}

// ---------------------------------------------------------------------------
extern "C" void kernel_launch(void* const* d_in, const int* in_sizes, int n_in,
                              void* d_out, int out_size) {
  const float* hidden  = (const float*)d_in[0];
  const float* cosb    = (const float*)d_in[1];
  const float* sinb    = (const float*)d_in[2];
  const float* wq_a    = (const float*)d_in[3];
  const float* q_ln_w  = (const float*)d_in[4];
  const float* wq_b    = (const float*)d_in[5];
  const float* wkv_a   = (const float*)d_in[6];
  const float* kv_ln_w = (const float*)d_in[7];
  const float* wkv_b   = (const float*)d_in[8];
  const float* wo      = (const float*)d_in[9];
  float* out = (float*)d_out;

  float *hid, *wqkva, *qkva, *qan, *wqb, *q, *kvn, *wkvb, *kv, *kpe, *ao, *woR;
  cudaGetSymbolAddress((void**)&hid,   g_hid);
  cudaGetSymbolAddress((void**)&wqkva, g_wqkva);
  cudaGetSymbolAddress((void**)&qkva,  g_qkva);
  cudaGetSymbolAddress((void**)&qan,   g_qan);
  cudaGetSymbolAddress((void**)&wqb,   g_wqb);
  cudaGetSymbolAddress((void**)&q,     g_q);
  cudaGetSymbolAddress((void**)&kvn,   g_kvn);
  cudaGetSymbolAddress((void**)&wkvb,  g_wkvb);
  cudaGetSymbolAddress((void**)&kv,    g_kv);
  cudaGetSymbolAddress((void**)&kpe,   g_kpe);
  cudaGetSymbolAddress((void**)&ao,    g_ao);
  cudaGetSymbolAddress((void**)&woR,   g_wo);

  const int GSM = STAGES * 2 * AW * 4;   // 96KB
  cudaFuncSetAttribute(gemm_tf32_cp, cudaFuncAttributeMaxDynamicSharedMemorySize, GSM);
  cudaFuncSetAttribute(flash_kernel, cudaFuncAttributeMaxDynamicSharedMemorySize, FLASH_SMEM);

  // fused tf32 pre-rounding of all operands (ONE launch)
  const int n0 = SQ*DIM/4;
  const int n1 = RQ*DIM/4;
  const int n2 = (RKV+DROPE)*DIM/4;
  const int n3 = HDQ*RQ/4;
  const int n4 = HKV*RKV/4;
  const int n5 = DIM*HDV/4;
  const int ntot = n0+n1+n2+n3+n4+n5;
  roundall_kernel<<<(ntot + 255)/256, 256>>>(
      (const float4*)hidden, (float4*)hid,   n0,
      (const float4*)wq_a,   (float4*)wqkva, n1,
      (const float4*)wkv_a,  (float4*)(wqkva + (size_t)RQ*DIM), n2,
      (const float4*)wq_b,   (float4*)wqb,   n3,
      (const float4*)wkv_b,  (float4*)wkvb,  n4,
      (const float4*)wo,     (float4*)woR,   n5);

  // fused q_a + kv_a projection: qkva[1024, 2176]
  gemm_tf32_cp<<<dim3(SQ/128, NCAT/128), 256, GSM>>>(hid, wqkva, qkva, SQ, NCAT, DIM);

  // q path
  rmsnorm_kernel<<<SQ, 256>>>(qkva, q_ln_w, qan, RQ, NCAT, RQ);
  gemm_tf32_cp<<<dim3(SQ/128, HDQ/128), 256, GSM>>>(qan, wqb, q, SQ, HDQ, RQ);

  // kv path
  rmsnorm_kernel<<<SQ, 256>>>(qkva + RQ, kv_ln_w, kvn, RKV, NCAT, RKV);
  gemm_tf32_cp<<<dim3(SQ/128, HKV/128), 256, GSM>>>(kvn, wkvb, kv, SQ, HKV, RKV);

  // RoPE
  rope_q_kernel<<<(SQ*NH*32)/256, 256>>>(q, cosb, sinb);
  rope_k_kernel<<<(SQ*32)/256, 256>>>(qkva, cosb, sinb, kpe);

  // causal flash attention (rounds its output)
  flash_kernel<<<dim3(NH, SQ/64), 256, FLASH_SMEM>>>(q, kv, kpe, ao);

  // output projection
  gemm_tf32_cp<<<dim3(SQ/128, DIM/128), 256, GSM>>>(ao, woR, out, SQ, DIM, HDV);
}

// round 17
// speedup vs baseline: 1.6943x; 1.1639x over previous
#include <cuda_runtime.h>
#include <cuda_bf16.h>
#include <math.h>

// Problem constants
#define SQ   1024
#define DIM  7168
#define NH   128
#define DNOPE 128
#define DROPE 64
#define DVAL 128
#define DQH  192         // DNOPE + DROPE
#define RQ   1536
#define RKV  512
#define HDQ  (NH*DQH)            // 24576
#define HKV  (NH*(DNOPE+DVAL))   // 32768
#define HDV  (NH*DVAL)           // 16384
#define EPS  1e-6f
#define NCAT 2176                // RQ + RKV + DROPE = 2112, padded to 17*128

// Scratch (device globals: allocation-free per harness rules; zero-init -> pads stay 0)
__device__ float g_hid  [SQ*DIM];
__device__ float g_wqkva[NCAT*DIM];
__device__ float g_qkva [SQ*NCAT];
__device__ float g_qan  [SQ*RQ];
__device__ float g_wqb  [HDQ*RQ];
__device__ float g_q    [SQ*HDQ];
__device__ float g_kvn  [SQ*RKV];
__device__ float g_wkvb [HKV*RKV];
__device__ float g_kv   [SQ*HKV];
__device__ float g_kpe  [SQ*DROPE];
__device__ float g_ao   [SQ*HDV];
__device__ float g_wo   [DIM*HDV];

// ---------------------------------------------------------------------------
// helpers
// ---------------------------------------------------------------------------
__device__ __forceinline__ unsigned f2tf(float f) {
  unsigned u;
  asm("cvt.rna.tf32.f32 %0, %1;" : "=r"(u) : "f"(f));
  return u;
}
__device__ __forceinline__ float rtf(float f) { return __uint_as_float(f2tf(f)); }

__device__ __forceinline__ unsigned smem_u32(const void* p){
  unsigned a;
  asm("{ .reg .u64 t; cvta.to.shared.u64 t, %1; cvt.u32.u64 %0, t; }" : "=r"(a) : "l"(p));
  return a;
}
__device__ __forceinline__ void cp16(unsigned dst, const float* src){
  asm volatile("cp.async.cg.shared.global [%0], [%1], 16;" :: "r"(dst), "l"(src));
}
__device__ __forceinline__ void cp_commit(){ asm volatile("cp.async.commit_group;" ::: "memory"); }
__device__ __forceinline__ void cp_wait2(){ asm volatile("cp.async.wait_group 2;" ::: "memory"); }

__device__ __forceinline__ void mma_tf32(float* d, const unsigned* a, const unsigned* b) {
  asm volatile(
    "mma.sync.aligned.m16n8k8.row.col.f32.tf32.tf32.f32 "
    "{%0,%1,%2,%3},{%4,%5,%6,%7},{%8,%9},{%0,%1,%2,%3};"
    : "+f"(d[0]), "+f"(d[1]), "+f"(d[2]), "+f"(d[3])
    : "r"(a[0]), "r"(a[1]), "r"(a[2]), "r"(a[3]), "r"(b[0]), "r"(b[1]));
}

__device__ __forceinline__ float4 rtf4(float4 v) {
  return make_float4(rtf(v.x), rtf(v.y), rtf(v.z), rtf(v.w));
}

// Fused tf32 pre-rounding of all six operands in ONE launch.
__global__ void __launch_bounds__(256) roundall_kernel(
    const float4* s0, float4* d0, int n0,
    const float4* s1, float4* d1, int n1,
    const float4* s2, float4* d2, int n2,
    const float4* s3, float4* d3, int n3,
    const float4* s4, float4* d4, int n4,
    const float4* s5, float4* d5, int n5) {
  int i = blockIdx.x * 256 + threadIdx.x;
  if (i < n0) { d0[i] = rtf4(s0[i]); return; } i -= n0;
  if (i < n1) { d1[i] = rtf4(s1[i]); return; } i -= n1;
  if (i < n2) { d2[i] = rtf4(s2[i]); return; } i -= n2;
  if (i < n3) { d3[i] = rtf4(s3[i]); return; } i -= n3;
  if (i < n4) { d4[i] = rtf4(s4[i]); return; } i -= n4;
  if (i < n5) { d5[i] = rtf4(s5[i]); }
}

// ---------------------------------------------------------------------------
// TF32 tensor-core NT GEMM, cp.async 6-stage ring, TWO k-stages per sync
// (R16-proven). CTA tile 128x128x16/stage, 256 threads, warp tile 64x32.
// Requires M%128==0, N%128==0, K%32==0 (KT even), K>=96.
// smem: 6 stages x 16KB = 96KB dynamic; 2 CTAs/SM.
// ---------------------------------------------------------------------------
#define STAGES 6
#define AW 2048   // words per stage per operand (128 rows * 16 k)

__global__ void __launch_bounds__(256, 2) gemm_tf32_cp(
    const float* __restrict__ A, const float* __restrict__ B,
    float* __restrict__ C, int M, int N, int K) {
  extern __shared__ unsigned sm[];
  const int KT = K >> 4;
  const int bm = blockIdx.x * 128;
  const int bn = blockIdx.y * 128;
  const int tid  = threadIdx.x;
  const int lane = tid & 31;
  const int w    = tid >> 5;
  const int wm   = (w & 1) * 64;
  const int wn   = (w >> 1) * 32;
  const int g    = lane >> 2;
  const int tig  = lane & 3;

  const int sr = tid >> 2;
  const int kc = tid & 3;
  const float* gA0 = A + (size_t)(bm + sr) * K + kc * 4;
  const float* gA1 = gA0 + (size_t)64 * K;
  const float* gB0 = B + (size_t)(bn + sr) * K + kc * 4;
  const float* gB1 = gB0 + (size_t)64 * K;
  const unsigned sb = smem_u32(sm);
  #define SWZ(r) (((r) ^ ((r) >> 2)) & 3)
  const unsigned dA0 = sb + 4u * ( sr      * 16 + ((kc ^ SWZ(sr))      << 2) );
  const unsigned dA1 = sb + 4u * ((sr + 64)* 16 + ((kc ^ SWZ(sr + 64)) << 2) );
  const unsigned dB0 = dA0 + 4u * STAGES * AW;
  const unsigned dB1 = dA1 + 4u * STAGES * AW;

  int aoff0[4], aoff1[4], asz0[4], asz1[4], boff[4], bsz[4];
#pragma unroll
  for (int mt = 0; mt < 4; mt++) {
    int r0 = wm + mt * 16 + g, r1 = r0 + 8;
    aoff0[mt] = r0 * 16 + tig; asz0[mt] = SWZ(r0);
    aoff1[mt] = r1 * 16 + tig; asz1[mt] = SWZ(r1);
  }
#pragma unroll
  for (int nt = 0; nt < 4; nt++) {
    int cn = wn + nt * 8 + g;
    boff[nt] = cn * 16 + tig; bsz[nt] = SWZ(cn);
  }

  float acc[4][4][4];
#pragma unroll
  for (int mt = 0; mt < 4; mt++)
#pragma unroll
    for (int nt = 0; nt < 4; nt++)
#pragma unroll
      for (int i = 0; i < 4; i++) acc[mt][nt][i] = 0.f;

  auto issue = [&](int s, int slot) {
    if (s < KT) {
      const unsigned so = ((unsigned)slot * AW) << 2;
      const size_t go = (size_t)s * 16;
      cp16(dA0 + so, gA0 + go);
      cp16(dA1 + so, gA1 + go);
      cp16(dB0 + so, gB0 + go);
      cp16(dB1 + so, gB1 + go);
    }
    cp_commit();
  };

  auto compute = [&](int slot) {
    const unsigned aB = (unsigned)slot * AW;
    const unsigned bB = STAGES * AW + (unsigned)slot * AW;
#pragma unroll
    for (int ks = 0; ks < 2; ++ks) {
      const int kc0 = ks << 1;
      unsigned af[4][4], bf[4][2];
#pragma unroll
      for (int mt = 0; mt < 4; mt++) {
        af[mt][0] = sm[aB + aoff0[mt] + (((kc0    ) ^ asz0[mt]) << 2)];
        af[mt][1] = sm[aB + aoff1[mt] + (((kc0    ) ^ asz1[mt]) << 2)];
        af[mt][2] = sm[aB + aoff0[mt] + (((kc0 + 1) ^ asz0[mt]) << 2)];
        af[mt][3] = sm[aB + aoff1[mt] + (((kc0 + 1) ^ asz1[mt]) << 2)];
      }
#pragma unroll
      for (int nt = 0; nt < 4; nt++) {
        bf[nt][0] = sm[bB + boff[nt] + (((kc0    ) ^ bsz[nt]) << 2)];
        bf[nt][1] = sm[bB + boff[nt] + (((kc0 + 1) ^ bsz[nt]) << 2)];
      }
#pragma unroll
      for (int mt = 0; mt < 4; mt++)
#pragma unroll
        for (int nt = 0; nt < 4; nt++)
          mma_tf32(acc[mt][nt], af[mt], bf[nt]);
    }
  };

  issue(0, 0); issue(1, 1); issue(2, 2); issue(3, 3);

  int cs = 0, fs = 4;
  for (int kt = 0; kt < KT; kt += 2) {
    cp_wait2();
    __syncthreads();
    issue(kt + 4, fs); fs = (fs + 1 == STAGES) ? 0 : fs + 1;
    issue(kt + 5, fs); fs = (fs + 1 == STAGES) ? 0 : fs + 1;
    compute(cs); cs = (cs + 1 == STAGES) ? 0 : cs + 1;
    compute(cs); cs = (cs + 1 == STAGES) ? 0 : cs + 1;
  }

#pragma unroll
  for (int mt = 0; mt < 4; mt++) {
    const int row = bm + wm + mt * 16 + g;
#pragma unroll
    for (int nt = 0; nt < 4; nt++) {
      const int col = bn + wn + nt * 8 + 2 * tig;
      *(float2*)(C + (size_t)row * N + col)       = make_float2(acc[mt][nt][0], acc[mt][nt][1]);
      *(float2*)(C + (size_t)(row + 8) * N + col) = make_float2(acc[mt][nt][2], acc[mt][nt][3]);
    }
  }
}

// ---------------------------------------------------------------------------
// RMSNorm: out = x * rsqrt(mean(x^2)+eps) * w, rounded to tf32 for next GEMM.
// ---------------------------------------------------------------------------
__global__ void __launch_bounds__(256) rmsnorm_kernel(
    const float* __restrict__ in, const float* __restrict__ w,
    float* __restrict__ out, int n, int istride, int ostride) {
  const int row = blockIdx.x;
  const float* x = in + (size_t)row * istride;
  float s = 0.f;
  for (int i = threadIdx.x; i < n; i += 256) { float v = x[i]; s += v*v; }
  __shared__ float red[256];
  red[threadIdx.x] = s;
  __syncthreads();
  for (int off = 128; off > 0; off >>= 1) {
    if (threadIdx.x < off) red[threadIdx.x] += red[threadIdx.x + off];
    __syncthreads();
  }
  const float inv = rsqrtf(red[0] / (float)n + EPS);
  float* o = out + (size_t)row * ostride;
  for (int i = threadIdx.x; i < n; i += 256) o[i] = rtf(x[i] * inv * w[i]);
}

// ---------------------------------------------------------------------------
// RoPE on q_pe (in-place in g_q).
// ---------------------------------------------------------------------------
__global__ void rope_q_kernel(float* __restrict__ q,
                              const float* __restrict__ cosb,
                              const float* __restrict__ sinb) {
  int idx = blockIdx.x * blockDim.x + threadIdx.x;   // SQ*NH*32
  int d = idx & 31;
  int h = (idx >> 5) & (NH - 1);
  int s = idx >> 12;
  float* base = q + (size_t)s * HDQ + h * DQH + DNOPE;
  float x1 = base[d], x2 = base[d + 32];
  float c1 = cosb[s*DROPE + d],      s1 = sinb[s*DROPE + d];
  float c2 = cosb[s*DROPE + d + 32], s2 = sinb[s*DROPE + d + 32];
  base[d]      = x1*c1 - x2*s1;
  base[d + 32] = x2*c2 + x1*s2;
}

// RoPE on k_pe (from qkva cols [2048, 2112)) -> g_kpe[S, 64]
__global__ void rope_k_kernel(const float* __restrict__ qkva,
                              const float* __restrict__ cosb,
                              const float* __restrict__ sinb,
                              float* __restrict__ kpe) {
  int idx = blockIdx.x * blockDim.x + threadIdx.x;  // SQ*32
  int d = idx & 31;
  int s = idx >> 5;
  float x1 = qkva[(size_t)s*NCAT + (RQ+RKV) + d];
  float x2 = qkva[(size_t)s*NCAT + (RQ+RKV) + 32 + d];
  float c1 = cosb[s*DROPE + d],      s1 = sinb[s*DROPE + d];
  float c2 = cosb[s*DROPE + d + 32], s2 = sinb[s*DROPE + d + 32];
  kpe[s*DROPE + d]      = x1*c1 - x2*s1;
  kpe[s*DROPE + 32 + d] = x2*c2 + x1*s2;
}

// ---------------------------------------------------------------------------
// Flash attention (causal), register-blocked + DE-CONFLICTED smem.
// One block per (head, 64-row q tile), 256 threads as 16x16: thread (ty,tx)
// owns a 4x4 score tile (cols tx*4..) and output cols {4tx..4tx+3, 64+4tx..}.
// Q/K layout: row stride 192 words + chunk-XOR swizzle
//   word(row,d) = row*192 + ((d>>2 ^ SWF(row))<<2) + (d&3),
//   SWF(r) = (r ^ (r>>3)) & 7
// -> K-fragment loads across the 16 tx lanes hit all 8 chunk clusters (2-way);
//    Q loads broadcast. PV V-loads at cols 4tx / 64+4tx: 2-way.
// Ps stride 65 (odd) -> scalar stores, broadcast reads.
// ---------------------------------------------------------------------------
#define QK_STR 192
#define SWF(r) (((r) ^ ((r) >> 3)) & 7)
#define PS_STR 65
#define FLASH_SMEM ((2*64*QK_STR + 64*128 + 64*PS_STR) * 4)

__global__ void __launch_bounds__(256) flash_kernel(
    const float* __restrict__ q, const float* __restrict__ kv,
    const float* __restrict__ kpe, float* __restrict__ ao) {
  extern __shared__ float smf[];
  float* Qs = smf;                     // 64 x 192 (swizzled)
  float* Ks = Qs + 64*QK_STR;          // 64 x 192 (swizzled)
  float* Vs = Ks + 64*QK_STR;          // 64 x 128 (linear)
  float* Ps = Vs + 64*128;             // 64 x PS_STR

  const int h  = blockIdx.x;
  const int q0 = blockIdx.y * 64;
  const int tid = threadIdx.x;
  const int tx = tid & 15;
  const int ty = tid >> 4;
  const int r0 = ty * 4;               // q-row group
  const int c0 = tx * 4;               // score-col group
  const int oc = tx * 4;               // out-col group A (group B = 64+oc)

  for (int idx = tid; idx < 64*DQH; idx += 256) {
    int row = idx / DQH, d = idx % DQH;
    Qs[row*QK_STR + (((d>>2) ^ SWF(row))<<2) + (d&3)] =
        q[(size_t)(q0+row)*HDQ + h*DQH + d];
  }

  float m[4], l[4], o[4][8];
#pragma unroll
  for (int r = 0; r < 4; r++) {
    m[r] = -INFINITY; l[r] = 0.f;
#pragma unroll
    for (int c = 0; c < 8; c++) o[r][c] = 0.f;
  }
  const float scale = rsqrtf((float)DQH);

  const int nkt = blockIdx.y + 1;
  for (int kt = 0; kt < nkt; kt++) {
    const int k0 = kt * 64;
    __syncthreads();
    for (int idx = tid; idx < 64*DQH; idx += 256) {
      int row = idx / DQH, d = idx % DQH;
      Ks[row*QK_STR + (((d>>2) ^ SWF(row))<<2) + (d&3)] = (d < DNOPE)
          ? kv[(size_t)(k0+row)*HKV + h*(DNOPE+DVAL) + d]
          : kpe[(k0+row)*DROPE + (d - DNOPE)];
    }
    for (int idx = tid; idx < 64*128; idx += 256) {
      int row = idx >> 7, d = idx & 127;
      Vs[idx] = kv[(size_t)(k0+row)*HKV + h*(DNOPE+DVAL) + DNOPE + d];
    }
    __syncthreads();

    // scores: 4x4 microtile, float4 over d (chunk-swizzled addressing)
    float sc[4][4];
#pragma unroll
    for (int r = 0; r < 4; r++)
#pragma unroll
      for (int c = 0; c < 4; c++) sc[r][c] = 0.f;

    for (int d0 = 0; d0 < DQH; d0 += 4) {
      const int ch = d0 >> 2;
      float4 qv[4], kv4[4];
#pragma unroll
      for (int r = 0; r < 4; r++)
        qv[r]  = *(const float4*)&Qs[(r0+r)*QK_STR + ((ch ^ SWF(r0+r))<<2)];
#pragma unroll
      for (int c = 0; c < 4; c++)
        kv4[c] = *(const float4*)&Ks[(c0+c)*QK_STR + ((ch ^ SWF(c0+c))<<2)];
#pragma unroll
      for (int r = 0; r < 4; r++)
#pragma unroll
        for (int c = 0; c < 4; c++) {
          sc[r][c] += qv[r].x*kv4[c].x + qv[r].y*kv4[c].y
                    + qv[r].z*kv4[c].z + qv[r].w*kv4[c].w;
        }
    }

    if (kt == nkt - 1) {     // only the diagonal tile needs the causal mask
#pragma unroll
      for (int r = 0; r < 4; r++)
#pragma unroll
        for (int c = 0; c < 4; c++)
          sc[r][c] = (k0 + c0 + c <= q0 + r0 + r) ? sc[r][c]*scale : -INFINITY;
    } else {
#pragma unroll
      for (int r = 0; r < 4; r++)
#pragma unroll
        for (int c = 0; c < 4; c++) sc[r][c] *= scale;
    }

    // online softmax: reduce over tx (16 lanes)
    float alpha[4];
#pragma unroll
    for (int r = 0; r < 4; r++) {
      float mloc = fmaxf(fmaxf(sc[r][0], sc[r][1]), fmaxf(sc[r][2], sc[r][3]));
      mloc = fmaxf(mloc, __shfl_xor_sync(0xffffffffu, mloc, 1));
      mloc = fmaxf(mloc, __shfl_xor_sync(0xffffffffu, mloc, 2));
      mloc = fmaxf(mloc, __shfl_xor_sync(0xffffffffu, mloc, 4));
      mloc = fmaxf(mloc, __shfl_xor_sync(0xffffffffu, mloc, 8));
      float mnew = fmaxf(m[r], mloc);
      alpha[r] = expf(m[r] - mnew);
      float lloc = 0.f;
#pragma unroll
      for (int c = 0; c < 4; c++) {
        float p = expf(sc[r][c] - mnew);
        sc[r][c] = p;
        lloc += p;
      }
      lloc += __shfl_xor_sync(0xffffffffu, lloc, 1);
      lloc += __shfl_xor_sync(0xffffffffu, lloc, 2);
      lloc += __shfl_xor_sync(0xffffffffu, lloc, 4);
      lloc += __shfl_xor_sync(0xffffffffu, lloc, 8);
      l[r] = l[r] * alpha[r] + lloc;
      m[r] = mnew;
#pragma unroll
      for (int c = 0; c < 8; c++) o[r][c] *= alpha[r];
      // scalar stores: Ps row stride 65 words is not 16B-aligned
      Ps[(r0+r)*PS_STR + c0    ] = sc[r][0];
      Ps[(r0+r)*PS_STR + c0 + 1] = sc[r][1];
      Ps[(r0+r)*PS_STR + c0 + 2] = sc[r][2];
      Ps[(r0+r)*PS_STR + c0 + 3] = sc[r][3];
    }
    __syncthreads();   // Ps visible to all before PV

    // PV: thread accumulates rows r0..r0+3 x cols {oc..oc+3, 64+oc..64+oc+3}
    for (int j = 0; j < 64; j++) {
      float4 v0 = *(const float4*)&Vs[j*128 + oc];
      float4 v1 = *(const float4*)&Vs[j*128 + 64 + oc];
      float pv[4];
#pragma unroll
      for (int r = 0; r < 4; r++) pv[r] = Ps[(r0+r)*PS_STR + j];
#pragma unroll
      for (int r = 0; r < 4; r++) {
        o[r][0] += pv[r]*v0.x; o[r][1] += pv[r]*v0.y;
        o[r][2] += pv[r]*v0.z; o[r][3] += pv[r]*v0.w;
        o[r][4] += pv[r]*v1.x; o[r][5] += pv[r]*v1.y;
        o[r][6] += pv[r]*v1.z; o[r][7] += pv[r]*v1.w;
      }
    }
  }

#pragma unroll
  for (int r = 0; r < 4; r++) {
    const float invl = 1.f / l[r];
    float* op = ao + (size_t)(q0 + r0 + r)*HDV + h*DVAL;
    op[oc     ] = rtf(o[r][0] * invl);
    op[oc +  1] = rtf(o[r][1] * invl);
    op[oc +  2] = rtf(o[r][2] * invl);
    op[oc +  3] = rtf(o[r][3] * invl);
    op[oc + 64] = rtf(o[r][4] * invl);
    op[oc + 65] = rtf(o[r][5] * invl);
    op[oc + 66] = rtf(o[r][6] * invl);
    op[oc + 67] = rtf(o[r][7] * invl);
  }
}

// ---------------------------------------------------------------------------
extern "C" void kernel_launch(void* const* d_in, const int* in_sizes, int n_in,
                              void* d_out, int out_size) {
  const float* hidden  = (const float*)d_in[0];
  const float* cosb    = (const float*)d_in[1];
  const float* sinb    = (const float*)d_in[2];
  const float* wq_a    = (const float*)d_in[3];
  const float* q_ln_w  = (const float*)d_in[4];
  const float* wq_b    = (const float*)d_in[5];
  const float* wkv_a   = (const float*)d_in[6];
  const float* kv_ln_w = (const float*)d_in[7];
  const float* wkv_b   = (const float*)d_in[8];
  const float* wo      = (const float*)d_in[9];
  float* out = (float*)d_out;

  float *hid, *wqkva, *qkva, *qan, *wqb, *q, *kvn, *wkvb, *kv, *kpe, *ao, *woR;
  cudaGetSymbolAddress((void**)&hid,   g_hid);
  cudaGetSymbolAddress((void**)&wqkva, g_wqkva);
  cudaGetSymbolAddress((void**)&qkva,  g_qkva);
  cudaGetSymbolAddress((void**)&qan,   g_qan);
  cudaGetSymbolAddress((void**)&wqb,   g_wqb);
  cudaGetSymbolAddress((void**)&q,     g_q);
  cudaGetSymbolAddress((void**)&kvn,   g_kvn);
  cudaGetSymbolAddress((void**)&wkvb,  g_wkvb);
  cudaGetSymbolAddress((void**)&kv,    g_kv);
  cudaGetSymbolAddress((void**)&kpe,   g_kpe);
  cudaGetSymbolAddress((void**)&ao,    g_ao);
  cudaGetSymbolAddress((void**)&woR,   g_wo);

  const int GSM = STAGES * 2 * AW * 4;   // 96KB
  cudaFuncSetAttribute(gemm_tf32_cp, cudaFuncAttributeMaxDynamicSharedMemorySize, GSM);
  cudaFuncSetAttribute(flash_kernel, cudaFuncAttributeMaxDynamicSharedMemorySize, FLASH_SMEM);

  // fused tf32 pre-rounding of all operands (ONE launch)
  const int n0 = SQ*DIM/4;
  const int n1 = RQ*DIM/4;
  const int n2 = (RKV+DROPE)*DIM/4;
  const int n3 = HDQ*RQ/4;
  const int n4 = HKV*RKV/4;
  const int n5 = DIM*HDV/4;
  const int ntot = n0+n1+n2+n3+n4+n5;
  roundall_kernel<<<(ntot + 255)/256, 256>>>(
      (const float4*)hidden, (float4*)hid,   n0,
      (const float4*)wq_a,   (float4*)wqkva, n1,
      (const float4*)wkv_a,  (float4*)(wqkva + (size_t)RQ*DIM), n2,
      (const float4*)wq_b,   (float4*)wqb,   n3,
      (const float4*)wkv_b,  (float4*)wkvb,  n4,
      (const float4*)wo,     (float4*)woR,   n5);

  // fused q_a + kv_a projection: qkva[1024, 2176]
  gemm_tf32_cp<<<dim3(SQ/128, NCAT/128), 256, GSM>>>(hid, wqkva, qkva, SQ, NCAT, DIM);

  // q path
  rmsnorm_kernel<<<SQ, 256>>>(qkva, q_ln_w, qan, RQ, NCAT, RQ);
  gemm_tf32_cp<<<dim3(SQ/128, HDQ/128), 256, GSM>>>(qan, wqb, q, SQ, HDQ, RQ);

  // kv path
  rmsnorm_kernel<<<SQ, 256>>>(qkva + RQ, kv_ln_w, kvn, RKV, NCAT, RKV);
  gemm_tf32_cp<<<dim3(SQ/128, HKV/128), 256, GSM>>>(kvn, wkvb, kv, SQ, HKV, RKV);

  // RoPE
  rope_q_kernel<<<(SQ*NH*32)/256, 256>>>(q, cosb, sinb);
  rope_k_kernel<<<(SQ*32)/256, 256>>>(qkva, cosb, sinb, kpe);

  // causal flash attention (rounds its output)
  flash_kernel<<<dim3(NH, SQ/64), 256, FLASH_SMEM>>>(q, kv, kpe, ao);

  // output projection
  gemm_tf32_cp<<<dim3(SQ/128, DIM/128), 256, GSM>>>(ao, woR, out, SQ, DIM, HDV);
}